// round 12
// baseline (speedup 1.0000x reference)
#include <cuda_runtime.h>
#include <cuda_bf16.h>
#include <cstdint>

// GriddingDistance round 12: round-5 schedule (validated optimum) + paired-
// point scatter. Each thread handles 2 consecutive points loaded with three
// LDG.64 (24B, 8B-aligned since the pair index is even), cutting point-load
// LSU ops from 3/point to 1.5/point. RED emission unchanged (z-window v2/v4,
// provably minimal instruction count).
//   L0 memset pred half (64MB exposed)
//   L1 scatter pred (2pt/thread, 2048 blk x 128) || zero gt half
//   L2 scatter gt   (2pt/thread, 2048 blk x 128)

#define GRID_R 128
#define GSZ    (GRID_R * GRID_R * GRID_R)

__device__ __forceinline__ void red_add_f32(float* p, float v) {
    atomicAdd(p, v);  // return unused -> REDG
}
__device__ __forceinline__ void red_add_v2_f32(float* p, float a, float b) {
    asm volatile("red.global.add.v2.f32 [%0], {%1, %2};"
                 :: "l"(p), "f"(a), "f"(b) : "memory");
}
__device__ __forceinline__ void red_add_v4_f32(float* p, float a, float b,
                                               float c, float d) {
    asm volatile("red.global.add.v4.f32 [%0], {%1, %2, %3, %4};"
                 :: "l"(p), "f"(a), "f"(b), "f"(c), "f"(d) : "memory");
}

// Scatter one already-loaded point into sample grid gb.
__device__ __forceinline__ void scatter_point(float px, float py, float pz,
                                              float* __restrict__ gb)
{
    px = fmaf(px, 128.0f, 64.0f);
    py = fmaf(py, 128.0f, 64.0f);
    pz = fmaf(pz, 128.0f, 64.0f);

    float fx = floorf(px), fy = floorf(py), fz = floorf(pz);
    float dx = px - fx,   dy = py - fy,   dz = pz - fz;
    int ix = (int)fx, iy = (int)fy, iz = (int)fz;

    float wx0 = 1.0f - dx, wy0 = 1.0f - dy, wz0 = 1.0f - dz;
    float w00 = wx0 * wy0, w01 = wx0 * dy, w10 = dx * wy0, w11 = dx * dy;

    bool interior = (ix >= 0) & (ix + 1 < GRID_R) &
                    (iy >= 0) & (iy + 1 < GRID_R) &
                    (iz >= 0) & (iz + 1 < GRID_R);

    if (interior) {
        int r00 = (ix * GRID_R + iy) * GRID_R + iz;
        int r01 = r00 + GRID_R;
        int r10 = r00 + GRID_R * GRID_R;
        int r11 = r10 + GRID_R;

        int m4 = iz & 3;
        if ((m4 & 1) == 0) {
            red_add_v2_f32(gb + r00, w00 * wz0, w00 * dz);
            red_add_v2_f32(gb + r01, w01 * wz0, w01 * dz);
            red_add_v2_f32(gb + r10, w10 * wz0, w10 * dz);
            red_add_v2_f32(gb + r11, w11 * wz0, w11 * dz);
        } else if (m4 == 1) {
            red_add_v4_f32(gb + r00 - 1, 0.f, w00 * wz0, w00 * dz, 0.f);
            red_add_v4_f32(gb + r01 - 1, 0.f, w01 * wz0, w01 * dz, 0.f);
            red_add_v4_f32(gb + r10 - 1, 0.f, w10 * wz0, w10 * dz, 0.f);
            red_add_v4_f32(gb + r11 - 1, 0.f, w11 * wz0, w11 * dz, 0.f);
        } else {
            red_add_f32(gb + r00,     w00 * wz0);
            red_add_f32(gb + r00 + 1, w00 * dz);
            red_add_f32(gb + r01,     w01 * wz0);
            red_add_f32(gb + r01 + 1, w01 * dz);
            red_add_f32(gb + r10,     w10 * wz0);
            red_add_f32(gb + r10 + 1, w10 * dz);
            red_add_f32(gb + r11,     w11 * wz0);
            red_add_f32(gb + r11 + 1, w11 * dz);
        }
    } else {
        int ix0 = min(max(ix,     0), GRID_R - 1);
        int ix1 = min(max(ix + 1, 0), GRID_R - 1);
        int iy0 = min(max(iy,     0), GRID_R - 1);
        int iy1 = min(max(iy + 1, 0), GRID_R - 1);
        int iz0 = min(max(iz,     0), GRID_R - 1);
        int iz1 = min(max(iz + 1, 0), GRID_R - 1);
        int rx0 = ix0 * GRID_R * GRID_R, rx1 = ix1 * GRID_R * GRID_R;
        int ry0 = iy0 * GRID_R,          ry1 = iy1 * GRID_R;
        red_add_f32(gb + (rx0 + ry0 + iz0), w00 * wz0);
        red_add_f32(gb + (rx0 + ry0 + iz1), w00 * dz);
        red_add_f32(gb + (rx0 + ry1 + iz0), w01 * wz0);
        red_add_f32(gb + (rx0 + ry1 + iz1), w01 * dz);
        red_add_f32(gb + (rx1 + ry0 + iz0), w10 * wz0);
        red_add_f32(gb + (rx1 + ry0 + iz1), w10 * dz);
        red_add_f32(gb + (rx1 + ry1 + iz0), w11 * wz0);
        red_add_f32(gb + (rx1 + ry1 + iz1), w11 * dz);
    }
}

// Paired-point scatter: thread i handles points 2i and 2i+1.
// Requires total points even and n_per_sample even (pair never straddles
// a sample boundary: pair base is even, sample boundaries are even).
__device__ __forceinline__ void scatter_pairs(const float* __restrict__ pts,
                                              float* __restrict__ g,
                                              int n_per_sample,
                                              int npairs)
{
    int i = blockIdx.x * blockDim.x + threadIdx.x;
    if (i >= npairs) return;
    int t2 = 2 * i;                               // even global point index

    // 24 bytes at 8B-aligned address -> three LDG.64
    const float2* p2 = (const float2*)(pts + 3 * t2);
    float2 a = p2[0];
    float2 bq = p2[1];
    float2 c = p2[2];

    int sample = t2 / n_per_sample;               // same for both points
    float* __restrict__ gb = g + (long long)sample * GSZ;

    scatter_point(a.x, a.y, bq.x, gb);
    scatter_point(bq.y, c.x, c.y, gb);
}

__device__ __forceinline__ void zero_range(float* __restrict__ base,
                                           long long nfloats)
{
    float4* z = (float4*)base;
    long long n4 = nfloats >> 2;
    long long nthreads = (long long)gridDim.x * blockDim.x;
    float4 zero = make_float4(0.f, 0.f, 0.f, 0.f);
    for (long long i = (long long)blockIdx.x * blockDim.x + threadIdx.x;
         i < n4; i += nthreads)
        z[i] = zero;
}

// y==0: paired scatter of all npairs; y==1: zero zbase[0, znum).
__global__ __launch_bounds__(128)
void scatter2_and_zero_kernel(const float* __restrict__ pts,
                              float* __restrict__ g,
                              int n_per_sample,
                              int npairs,
                              float* __restrict__ zbase,
                              long long znum)
{
    if (blockIdx.y == 0) {
        scatter_pairs(pts, g, n_per_sample, npairs);
    } else {
        zero_range(zbase, znum);
    }
}

__global__ __launch_bounds__(128)
void scatter2_only_kernel(const float* __restrict__ pts,
                          float* __restrict__ g,
                          int n_per_sample,
                          int npairs)
{
    scatter_pairs(pts, g, n_per_sample, npairs);
}

// Fallback single-point kernels (odd counts / odd n)
__global__ __launch_bounds__(256)
void scatter1_and_zero_kernel(const float* __restrict__ pts,
                              float* __restrict__ g,
                              int n_per_sample, int total_points,
                              float* __restrict__ zbase, long long znum)
{
    if (blockIdx.y == 0) {
        int t = blockIdx.x * blockDim.x + threadIdx.x;
        if (t >= total_points) return;
        int sample = t / n_per_sample;
        const float* p = pts + 3 * t;
        scatter_point(p[0], p[1], p[2], g + (long long)sample * GSZ);
    } else {
        zero_range(zbase, znum);
    }
}

__global__ __launch_bounds__(256)
void scatter1_only_kernel(const float* __restrict__ pts,
                          float* __restrict__ g,
                          int n_per_sample, int total_points)
{
    int t = blockIdx.x * blockDim.x + threadIdx.x;
    if (t >= total_points) return;
    int sample = t / n_per_sample;
    const float* p = pts + 3 * t;
    scatter_point(p[0], p[1], p[2], g + (long long)sample * GSZ);
}

extern "C" void kernel_launch(void* const* d_in, const int* in_sizes, int n_in,
                              void* d_out, int out_size)
{
    const float* pred = (const float*)d_in[0];
    const float* gt   = (const float*)d_in[1];
    float* out = (float*)d_out;

    int b = out_size / (2 * GSZ);                      // 8
    int total_points = in_sizes[0] / 3;                // 524288
    int n = total_points / b;                          // 65536
    long long grid_per_cloud = (long long)b * GSZ;     // 16777216 floats

    // L0: zero pred half (exposed; L2-resident for L1)
    cudaMemsetAsync(out, 0, (size_t)grid_per_cloud * sizeof(float));

    bool paired = ((n & 1) == 0) && ((total_points & 1) == 0);

    if (paired) {
        int npairs = total_points / 2;                 // 262144
        int nblk = (npairs + 127) / 128;               // 2048

        // L1: scatter pred (paired) || zero gt half
        scatter2_and_zero_kernel<<<dim3(nblk, 2), 128>>>(
            pred, out, n, npairs, out + grid_per_cloud, grid_per_cloud);

        // L2: scatter gt (paired)
        scatter2_only_kernel<<<nblk, 128>>>(gt, out + grid_per_cloud,
                                            n, npairs);
    } else {
        int nblk = (total_points + 255) / 256;
        scatter1_and_zero_kernel<<<dim3(nblk, 2), 256>>>(
            pred, out, n, total_points, out + grid_per_cloud, grid_per_cloud);
        scatter1_only_kernel<<<nblk, 256>>>(gt, out + grid_per_cloud,
                                            n, total_points);
    }
}

// round 13
// speedup vs baseline: 1.0685x; 1.0685x over previous
#include <cuda_runtime.h>
#include <cuda_bf16.h>
#include <cstdint>

// GriddingDistance round 13: round-5 schedule + Programmatic Dependent Launch.
//   K0 zero pred half (kernel; triggers dependents at block end)
//   K1 (PSS): pred scatter (loads -> griddepcontrol.wait -> REDs) || gt zero
//   K2 (PSS): gt scatter  (loads -> wait -> REDs)
// PDL overlaps each kernel's dispatch + point-load ramp with the previous
// kernel's drain/tail. Scatter math = round-5 winner (z-window v2/v4 REDs).

#define GRID_R 128
#define GSZ    (GRID_R * GRID_R * GRID_R)

__device__ __forceinline__ void pdl_wait() {
    asm volatile("griddepcontrol.wait;" ::: "memory");
}
__device__ __forceinline__ void pdl_trigger() {
    asm volatile("griddepcontrol.launch_dependents;");
}

__device__ __forceinline__ void red_add_f32(float* p, float v) {
    atomicAdd(p, v);  // return unused -> REDG
}
__device__ __forceinline__ void red_add_v2_f32(float* p, float a, float b) {
    asm volatile("red.global.add.v2.f32 [%0], {%1, %2};"
                 :: "l"(p), "f"(a), "f"(b) : "memory");
}
__device__ __forceinline__ void red_add_v4_f32(float* p, float a, float b,
                                               float c, float d) {
    asm volatile("red.global.add.v4.f32 [%0], {%1, %2, %3, %4};"
                 :: "l"(p), "f"(a), "f"(b), "f"(c), "f"(d) : "memory");
}

__device__ __forceinline__ void scatter_point(float px, float py, float pz,
                                              float* __restrict__ gb)
{
    px = fmaf(px, 128.0f, 64.0f);
    py = fmaf(py, 128.0f, 64.0f);
    pz = fmaf(pz, 128.0f, 64.0f);

    float fx = floorf(px), fy = floorf(py), fz = floorf(pz);
    float dx = px - fx,   dy = py - fy,   dz = pz - fz;
    int ix = (int)fx, iy = (int)fy, iz = (int)fz;

    float wx0 = 1.0f - dx, wy0 = 1.0f - dy, wz0 = 1.0f - dz;
    float w00 = wx0 * wy0, w01 = wx0 * dy, w10 = dx * wy0, w11 = dx * dy;

    bool interior = (ix >= 0) & (ix + 1 < GRID_R) &
                    (iy >= 0) & (iy + 1 < GRID_R) &
                    (iz >= 0) & (iz + 1 < GRID_R);

    if (interior) {
        int r00 = (ix * GRID_R + iy) * GRID_R + iz;
        int r01 = r00 + GRID_R;
        int r10 = r00 + GRID_R * GRID_R;
        int r11 = r10 + GRID_R;

        int m4 = iz & 3;
        if ((m4 & 1) == 0) {
            red_add_v2_f32(gb + r00, w00 * wz0, w00 * dz);
            red_add_v2_f32(gb + r01, w01 * wz0, w01 * dz);
            red_add_v2_f32(gb + r10, w10 * wz0, w10 * dz);
            red_add_v2_f32(gb + r11, w11 * wz0, w11 * dz);
        } else if (m4 == 1) {
            red_add_v4_f32(gb + r00 - 1, 0.f, w00 * wz0, w00 * dz, 0.f);
            red_add_v4_f32(gb + r01 - 1, 0.f, w01 * wz0, w01 * dz, 0.f);
            red_add_v4_f32(gb + r10 - 1, 0.f, w10 * wz0, w10 * dz, 0.f);
            red_add_v4_f32(gb + r11 - 1, 0.f, w11 * wz0, w11 * dz, 0.f);
        } else {
            red_add_f32(gb + r00,     w00 * wz0);
            red_add_f32(gb + r00 + 1, w00 * dz);
            red_add_f32(gb + r01,     w01 * wz0);
            red_add_f32(gb + r01 + 1, w01 * dz);
            red_add_f32(gb + r10,     w10 * wz0);
            red_add_f32(gb + r10 + 1, w10 * dz);
            red_add_f32(gb + r11,     w11 * wz0);
            red_add_f32(gb + r11 + 1, w11 * dz);
        }
    } else {
        int ix0 = min(max(ix,     0), GRID_R - 1);
        int ix1 = min(max(ix + 1, 0), GRID_R - 1);
        int iy0 = min(max(iy,     0), GRID_R - 1);
        int iy1 = min(max(iy + 1, 0), GRID_R - 1);
        int iz0 = min(max(iz,     0), GRID_R - 1);
        int iz1 = min(max(iz + 1, 0), GRID_R - 1);
        int rx0 = ix0 * GRID_R * GRID_R, rx1 = ix1 * GRID_R * GRID_R;
        int ry0 = iy0 * GRID_R,          ry1 = iy1 * GRID_R;
        red_add_f32(gb + (rx0 + ry0 + iz0), w00 * wz0);
        red_add_f32(gb + (rx0 + ry0 + iz1), w00 * dz);
        red_add_f32(gb + (rx0 + ry1 + iz0), w01 * wz0);
        red_add_f32(gb + (rx0 + ry1 + iz1), w01 * dz);
        red_add_f32(gb + (rx1 + ry0 + iz0), w10 * wz0);
        red_add_f32(gb + (rx1 + ry0 + iz1), w10 * dz);
        red_add_f32(gb + (rx1 + ry1 + iz0), w11 * wz0);
        red_add_f32(gb + (rx1 + ry1 + iz1), w11 * dz);
    }
}

// K0: zero pred half; signal dependents when done.
__global__ __launch_bounds__(256)
void zero_pred_kernel(float* __restrict__ out, long long nfloats)
{
    float4* z = (float4*)out;
    long long n4 = nfloats >> 2;
    long long stride = (long long)gridDim.x * blockDim.x;
    float4 zero = make_float4(0.f, 0.f, 0.f, 0.f);
    for (long long i = (long long)blockIdx.x * blockDim.x + threadIdx.x;
         i < n4; i += stride)
        z[i] = zero;
    __threadfence();
    pdl_trigger();
}

// K1: y==0 scatter pred (wait on K0 before atomics); y==1 zero gt (no wait).
__global__ __launch_bounds__(256)
void scatter_pred_zero_gt_kernel(const float* __restrict__ pred,
                                 float* __restrict__ out,
                                 int n_per_sample,
                                 int total_points,
                                 long long grid_per_cloud)
{
    if (blockIdx.y == 0) {
        int t = blockIdx.x * blockDim.x + threadIdx.x;
        if (t < total_points) {
            const float* p = pred + 3 * t;
            float px = p[0], py = p[1], pz = p[2];   // loads issue pre-wait
            int sample = t / n_per_sample;
            pdl_wait();                               // K0 zeros visible
            scatter_point(px, py, pz, out + (long long)sample * GSZ);
        }
    } else {
        // gt-half zero: independent of K0's pred zero -> no wait
        float4* z = (float4*)(out + grid_per_cloud);
        long long n4 = grid_per_cloud >> 2;
        long long stride = (long long)gridDim.x * blockDim.x;
        float4 zero = make_float4(0.f, 0.f, 0.f, 0.f);
        for (long long i = (long long)blockIdx.x * blockDim.x + threadIdx.x;
             i < n4; i += stride)
            z[i] = zero;
    }
    __threadfence();
    pdl_trigger();
}

// K2: scatter gt (wait on K1 before atomics).
__global__ __launch_bounds__(256)
void scatter_gt_kernel(const float* __restrict__ gt,
                       float* __restrict__ g,     // gt grid base
                       int n_per_sample,
                       int total_points)
{
    int t = blockIdx.x * blockDim.x + threadIdx.x;
    if (t < total_points) {
        const float* p = gt + 3 * t;
        float px = p[0], py = p[1], pz = p[2];       // loads issue pre-wait
        int sample = t / n_per_sample;
        pdl_wait();                                   // K1 (incl gt zero) done
        scatter_point(px, py, pz, g + (long long)sample * GSZ);
    } else {
        pdl_wait();
    }
}

extern "C" void kernel_launch(void* const* d_in, const int* in_sizes, int n_in,
                              void* d_out, int out_size)
{
    const float* pred = (const float*)d_in[0];
    const float* gt   = (const float*)d_in[1];
    float* out = (float*)d_out;

    int b = out_size / (2 * GSZ);                      // 8
    int total_points = in_sizes[0] / 3;                // 524288
    int n = total_points / b;                          // 65536
    long long grid_per_cloud = (long long)b * GSZ;     // 16777216 floats

    int nblk = (total_points + 255) / 256;             // 2048

    // K0: zero pred half (primary for K1's PDL edge)
    zero_pred_kernel<<<2048, 256>>>(out, grid_per_cloud);

    // K1: pred scatter || gt zero, launched with programmatic serialization
    {
        cudaLaunchConfig_t cfg = {};
        cudaLaunchAttribute attr[1];
        attr[0].id = cudaLaunchAttributeProgrammaticStreamSerialization;
        attr[0].val.programmaticStreamSerializationAllowed = 1;
        cfg.attrs = attr;
        cfg.numAttrs = 1;
        cfg.gridDim = dim3(nblk, 2, 1);
        cfg.blockDim = dim3(256, 1, 1);
        cfg.stream = 0;
        cudaLaunchKernelEx(&cfg, scatter_pred_zero_gt_kernel,
                           pred, out, n, total_points, grid_per_cloud);
    }

    // K2: gt scatter, programmatic serialization against K1
    {
        cudaLaunchConfig_t cfg = {};
        cudaLaunchAttribute attr[1];
        attr[0].id = cudaLaunchAttributeProgrammaticStreamSerialization;
        attr[0].val.programmaticStreamSerializationAllowed = 1;
        cfg.attrs = attr;
        cfg.numAttrs = 1;
        cfg.gridDim = dim3(nblk, 1, 1);
        cfg.blockDim = dim3(256, 1, 1);
        cfg.stream = 0;
        cudaLaunchKernelEx(&cfg, scatter_gt_kernel,
                           gt, out + grid_per_cloud, n, total_points);
    }
}

// round 14
// speedup vs baseline: 1.0734x; 1.0046x over previous
#include <cuda_runtime.h>
#include <cuda_bf16.h>
#include <cstdint>

// GriddingDistance round 14: PDL chain (validated to save ~1.7us at kernel
// edges in round 13) + fast zero kernel (uint32 index, unroll-8 STG.128) +
// maximal pre-wait prologue (all scatter arithmetic hoisted above
// griddepcontrol.wait; only the REDs are post-wait).
//   K0 zero pred half (fast kernel, explicit trigger)
//   K1 (PSS): pred scatter || gt zero
//   K2 (PSS): gt scatter
// Scatter math = round-5 winner (z-window v2/v4 vector REDs).

#define GRID_R 128
#define GSZ    (GRID_R * GRID_R * GRID_R)

__device__ __forceinline__ void pdl_wait() {
    asm volatile("griddepcontrol.wait;" ::: "memory");
}
__device__ __forceinline__ void pdl_trigger() {
    asm volatile("griddepcontrol.launch_dependents;");
}

__device__ __forceinline__ void red_add_f32(float* p, float v) {
    atomicAdd(p, v);  // return unused -> REDG
}
__device__ __forceinline__ void red_add_v2_f32(float* p, float a, float b) {
    asm volatile("red.global.add.v2.f32 [%0], {%1, %2};"
                 :: "l"(p), "f"(a), "f"(b) : "memory");
}
__device__ __forceinline__ void red_add_v4_f32(float* p, float a, float b,
                                               float c, float d) {
    asm volatile("red.global.add.v4.f32 [%0], {%1, %2, %3, %4};"
                 :: "l"(p), "f"(a), "f"(b), "f"(c), "f"(d) : "memory");
}

// Full scatter for one point; if WAIT, griddepcontrol.wait is placed after
// all arithmetic, immediately before the RED instructions.
template <bool WAIT>
__device__ __forceinline__ void scatter_point(float px, float py, float pz,
                                              float* __restrict__ gb)
{
    px = fmaf(px, 128.0f, 64.0f);
    py = fmaf(py, 128.0f, 64.0f);
    pz = fmaf(pz, 128.0f, 64.0f);

    float fx = floorf(px), fy = floorf(py), fz = floorf(pz);
    float dx = px - fx,   dy = py - fy,   dz = pz - fz;
    int ix = (int)fx, iy = (int)fy, iz = (int)fz;

    float wx0 = 1.0f - dx, wy0 = 1.0f - dy, wz0 = 1.0f - dz;
    float w00 = wx0 * wy0, w01 = wx0 * dy, w10 = dx * wy0, w11 = dx * dy;

    bool interior = (ix >= 0) & (ix + 1 < GRID_R) &
                    (iy >= 0) & (iy + 1 < GRID_R) &
                    (iz >= 0) & (iz + 1 < GRID_R);

    if (interior) {
        int r00 = (ix * GRID_R + iy) * GRID_R + iz;
        int r01 = r00 + GRID_R;
        int r10 = r00 + GRID_R * GRID_R;
        int r11 = r10 + GRID_R;

        float a00 = w00 * wz0, b00 = w00 * dz;
        float a01 = w01 * wz0, b01 = w01 * dz;
        float a10 = w10 * wz0, b10 = w10 * dz;
        float a11 = w11 * wz0, b11 = w11 * dz;

        if (WAIT) pdl_wait();

        int m4 = iz & 3;
        if ((m4 & 1) == 0) {
            red_add_v2_f32(gb + r00, a00, b00);
            red_add_v2_f32(gb + r01, a01, b01);
            red_add_v2_f32(gb + r10, a10, b10);
            red_add_v2_f32(gb + r11, a11, b11);
        } else if (m4 == 1) {
            red_add_v4_f32(gb + r00 - 1, 0.f, a00, b00, 0.f);
            red_add_v4_f32(gb + r01 - 1, 0.f, a01, b01, 0.f);
            red_add_v4_f32(gb + r10 - 1, 0.f, a10, b10, 0.f);
            red_add_v4_f32(gb + r11 - 1, 0.f, a11, b11, 0.f);
        } else {
            red_add_f32(gb + r00,     a00);
            red_add_f32(gb + r00 + 1, b00);
            red_add_f32(gb + r01,     a01);
            red_add_f32(gb + r01 + 1, b01);
            red_add_f32(gb + r10,     a10);
            red_add_f32(gb + r10 + 1, b10);
            red_add_f32(gb + r11,     a11);
            red_add_f32(gb + r11 + 1, b11);
        }
    } else {
        int ix0 = min(max(ix,     0), GRID_R - 1);
        int ix1 = min(max(ix + 1, 0), GRID_R - 1);
        int iy0 = min(max(iy,     0), GRID_R - 1);
        int iy1 = min(max(iy + 1, 0), GRID_R - 1);
        int iz0 = min(max(iz,     0), GRID_R - 1);
        int iz1 = min(max(iz + 1, 0), GRID_R - 1);
        int rx0 = ix0 * GRID_R * GRID_R, rx1 = ix1 * GRID_R * GRID_R;
        int ry0 = iy0 * GRID_R,          ry1 = iy1 * GRID_R;

        if (WAIT) pdl_wait();

        red_add_f32(gb + (rx0 + ry0 + iz0), w00 * wz0);
        red_add_f32(gb + (rx0 + ry0 + iz1), w00 * dz);
        red_add_f32(gb + (rx0 + ry1 + iz0), w01 * wz0);
        red_add_f32(gb + (rx0 + ry1 + iz1), w01 * dz);
        red_add_f32(gb + (rx1 + ry0 + iz0), w10 * wz0);
        red_add_f32(gb + (rx1 + ry0 + iz1), w10 * dz);
        red_add_f32(gb + (rx1 + ry1 + iz0), w11 * wz0);
        red_add_f32(gb + (rx1 + ry1 + iz1), w11 * dz);
    }
}

// K0: fast zero of pred half. uint32 indexing, unroll-8 stores; explicit
// early trigger for the dependent launch.
__global__ __launch_bounds__(256)
void zero_pred_kernel(float4* __restrict__ z, unsigned n4)
{
    unsigned i = blockIdx.x * blockDim.x + threadIdx.x;
    unsigned stride = gridDim.x * blockDim.x;
    float4 zero = make_float4(0.f, 0.f, 0.f, 0.f);
    #pragma unroll 8
    for (; i < n4; i += stride)
        z[i] = zero;
    __threadfence();
    pdl_trigger();
}

// K1: y==0 scatter pred (all math pre-wait); y==1 zero gt half (no wait).
__global__ __launch_bounds__(256)
void scatter_pred_zero_gt_kernel(const float* __restrict__ pred,
                                 float* __restrict__ out,
                                 int n_per_sample,
                                 int total_points,
                                 long long grid_per_cloud)
{
    if (blockIdx.y == 0) {
        int t = blockIdx.x * blockDim.x + threadIdx.x;
        if (t < total_points) {
            const float* p = pred + 3 * t;
            float px = p[0], py = p[1], pz = p[2];
            int sample = t / n_per_sample;
            scatter_point<true>(px, py, pz, out + (long long)sample * GSZ);
        } else {
            pdl_wait();
        }
    } else {
        // gt-half zero: independent of K0 -> no wait
        float4* z = (float4*)(out + grid_per_cloud);
        unsigned n4 = (unsigned)(grid_per_cloud >> 2);
        unsigned stride = gridDim.x * blockDim.x;
        float4 zero = make_float4(0.f, 0.f, 0.f, 0.f);
        #pragma unroll 8
        for (unsigned i = blockIdx.x * blockDim.x + threadIdx.x;
             i < n4; i += stride)
            z[i] = zero;
    }
    __threadfence();
    pdl_trigger();
}

// K2: scatter gt (all math pre-wait).
__global__ __launch_bounds__(256)
void scatter_gt_kernel(const float* __restrict__ gt,
                       float* __restrict__ g,
                       int n_per_sample,
                       int total_points)
{
    int t = blockIdx.x * blockDim.x + threadIdx.x;
    if (t < total_points) {
        const float* p = gt + 3 * t;
        float px = p[0], py = p[1], pz = p[2];
        int sample = t / n_per_sample;
        scatter_point<true>(px, py, pz, g + (long long)sample * GSZ);
    } else {
        pdl_wait();
    }
}

extern "C" void kernel_launch(void* const* d_in, const int* in_sizes, int n_in,
                              void* d_out, int out_size)
{
    const float* pred = (const float*)d_in[0];
    const float* gt   = (const float*)d_in[1];
    float* out = (float*)d_out;

    int b = out_size / (2 * GSZ);                      // 8
    int total_points = in_sizes[0] / 3;                // 524288
    int n = total_points / b;                          // 65536
    long long grid_per_cloud = (long long)b * GSZ;     // 16777216 floats

    int nblk = (total_points + 255) / 256;             // 2048

    // K0: zero pred half
    zero_pred_kernel<<<2048, 256>>>((float4*)out,
                                    (unsigned)(grid_per_cloud >> 2));

    // K1: pred scatter || gt zero (programmatic dependency on K0)
    {
        cudaLaunchConfig_t cfg = {};
        cudaLaunchAttribute attr[1];
        attr[0].id = cudaLaunchAttributeProgrammaticStreamSerialization;
        attr[0].val.programmaticStreamSerializationAllowed = 1;
        cfg.attrs = attr;
        cfg.numAttrs = 1;
        cfg.gridDim = dim3(nblk, 2, 1);
        cfg.blockDim = dim3(256, 1, 1);
        cfg.stream = 0;
        cudaLaunchKernelEx(&cfg, scatter_pred_zero_gt_kernel,
                           pred, out, n, total_points, grid_per_cloud);
    }

    // K2: gt scatter (programmatic dependency on K1)
    {
        cudaLaunchConfig_t cfg = {};
        cudaLaunchAttribute attr[1];
        attr[0].id = cudaLaunchAttributeProgrammaticStreamSerialization;
        attr[0].val.programmaticStreamSerializationAllowed = 1;
        cfg.attrs = attr;
        cfg.numAttrs = 1;
        cfg.gridDim = dim3(nblk, 1, 1);
        cfg.blockDim = dim3(256, 1, 1);
        cfg.stream = 0;
        cudaLaunchKernelEx(&cfg, scatter_gt_kernel,
                           gt, out + grid_per_cloud, n, total_points);
    }
}